// round 16
// baseline (speedup 1.0000x reference)
#include <cuda_runtime.h>
#include <cuda_bf16.h>
#include <math.h>
#include <stdint.h>

// ---------------------------------------------------------------------------
// Problem constants
// ---------------------------------------------------------------------------
#define FEAT     128
#define FEAT3    384
#define NRBF     20
#define KPAD     32      // padded K for edge MMA
#define MAXNODES 20000
#define GK       128     // K of both node GEMMs

// split bf16 operand buffers
__device__ __nv_bfloat16 g_sh[MAXNODES * FEAT];   // s_j hi
__device__ __nv_bfloat16 g_sl[MAXNODES * FEAT];   // s_j lo
__device__ __nv_bfloat16 g_hh[MAXNODES * FEAT];   // h hi
__device__ __nv_bfloat16 g_hl[MAXNODES * FEAT];   // h lo
__device__ __nv_bfloat16 g_w1h[FEAT  * FEAT];     // W1^T hi  [n][k]
__device__ __nv_bfloat16 g_w1l[FEAT  * FEAT];
__device__ __nv_bfloat16 g_w2h[FEAT3 * FEAT];     // W2^T hi  [n][k]
__device__ __nv_bfloat16 g_w2l[FEAT3 * FEAT];
__device__ __nv_bfloat16 g_wrh[FEAT3 * KPAD];     // Wr^T hi  [n][k], k>=20 zero
__device__ __nv_bfloat16 g_wrl[FEAT3 * KPAD];
__device__ float g_inv[MAXNODES * FEAT3];
__device__ int   g_nbrs_is64;

// ---------------------------------------------------------------------------
// helpers
// ---------------------------------------------------------------------------
__device__ __forceinline__ void split_bf(float a, __nv_bfloat16 &hi, __nv_bfloat16 &lo) {
    hi = __float2bfloat16_rn(a);
    lo = __float2bfloat16_rn(a - __bfloat162float(hi));
}
__device__ __forceinline__ void mma_bf16(float* c, const uint32_t* a, const uint32_t* b) {
    asm volatile(
        "mma.sync.aligned.m16n8k16.row.col.f32.bf16.bf16.f32 "
        "{%0,%1,%2,%3}, {%4,%5,%6,%7}, {%8,%9}, {%0,%1,%2,%3};"
        : "+f"(c[0]), "+f"(c[1]), "+f"(c[2]), "+f"(c[3])
        : "r"(a[0]), "r"(a[1]), "r"(a[2]), "r"(a[3]), "r"(b[0]), "r"(b[1]));
}

// ---------------------------------------------------------------------------
// nbrs dtype detector
// ---------------------------------------------------------------------------
__global__ void detect_nbrs_kernel(const unsigned int* __restrict__ p, int n_words)
{
    if (threadIdx.x == 0 && blockIdx.x == 0) {
        unsigned int acc = 0;
        int lim = n_words < 512 ? n_words : 512;
        for (int i = 1; i < lim; i += 2) acc |= p[i];
        g_nbrs_is64 = (acc == 0u) ? 1 : 0;
    }
}

// ---------------------------------------------------------------------------
// split fp32 -> bf16 hi/lo (vectorized, layout preserved)
// ---------------------------------------------------------------------------
__global__ void split_f32_kernel(const float4* __restrict__ in,
                                 __nv_bfloat16* __restrict__ hi,
                                 __nv_bfloat16* __restrict__ lo, int n4)
{
    int i = blockIdx.x * blockDim.x + threadIdx.x;
    if (i >= n4) return;
    float4 v = in[i];
    __nv_bfloat16 h0,l0,h1,l1,h2,l2,h3,l3;
    split_bf(v.x, h0, l0); split_bf(v.y, h1, l1);
    split_bf(v.z, h2, l2); split_bf(v.w, h3, l3);
    *(__nv_bfloat162*)&hi[i*4    ] = __nv_bfloat162(h0, h1);
    *(__nv_bfloat162*)&hi[i*4 + 2] = __nv_bfloat162(h2, h3);
    *(__nv_bfloat162*)&lo[i*4    ] = __nv_bfloat162(l0, l1);
    *(__nv_bfloat162*)&lo[i*4 + 2] = __nv_bfloat162(l2, l3);
}

// split + transpose weights: W1,W2 (stride K=128) and Wr (K padded to 32)
__global__ void split_w_kernel(const float* __restrict__ W1,
                               const float* __restrict__ W2,
                               const float* __restrict__ Wr)
{
    int idx = blockIdx.x * blockDim.x + threadIdx.x;
    if (idx < FEAT * FEAT) {
        int n = idx / FEAT, k = idx % FEAT;
        __nv_bfloat16 h, l;
        split_bf(W1[k * FEAT + n], h, l);
        g_w1h[n * FEAT + k] = h;
        g_w1l[n * FEAT + k] = l;
    }
    int i2 = idx - FEAT * FEAT;
    if (i2 >= 0 && i2 < FEAT3 * FEAT) {
        int n = i2 / FEAT, k = i2 % FEAT;
        __nv_bfloat16 h, l;
        split_bf(W2[k * FEAT3 + n], h, l);
        g_w2h[n * FEAT + k] = h;
        g_w2l[n * FEAT + k] = l;
    }
    int i3 = idx - FEAT * FEAT - FEAT3 * FEAT;
    if (i3 >= 0 && i3 < FEAT3 * KPAD) {
        int n = i3 / KPAD, k = i3 % KPAD;
        float v = (k < NRBF) ? Wr[k * FEAT3 + n] : 0.0f;
        __nv_bfloat16 h, l;
        split_bf(v, h, l);
        g_wrh[n * KPAD + k] = h;
        g_wrl[n * KPAD + k] = l;
    }
}

// ---------------------------------------------------------------------------
// Node GEMM (R15, measured): tensor-core on pre-split bf16.
// ---------------------------------------------------------------------------
__global__ __launch_bounds__(256) void hgemm_kernel(
    const __nv_bfloat16* __restrict__ Agh, const __nv_bfloat16* __restrict__ Agl,
    const __nv_bfloat16* __restrict__ Bgh, const __nv_bfloat16* __restrict__ Bgl,
    const float* __restrict__ bias,
    float* __restrict__ Cf,
    __nv_bfloat16* __restrict__ Chh, __nv_bfloat16* __restrict__ Chl,
    int M, int N, int act)
{
    __shared__ __nv_bfloat16 Ah[128][40], Al[128][40];
    __shared__ __nv_bfloat16 Bh[64][40],  Bl[64][40];

    const int tid  = threadIdx.x;
    const int warp = tid >> 5;
    const int l    = tid & 31;
    const int gr   = l >> 2;
    const int tg   = l & 3;
    const int wm   = (warp >> 1) * 32;
    const int wn   = (warp & 1) * 32;
    const int row0 = blockIdx.x * 128;
    const int col0 = blockIdx.y * 64;

    float acc[2][4][4];
    #pragma unroll
    for (int t = 0; t < 2; t++)
        #pragma unroll
        for (int u = 0; u < 4; u++)
            #pragma unroll
            for (int v = 0; v < 4; v++) acc[t][u][v] = 0.0f;

    const uint4 Z = make_uint4(0, 0, 0, 0);

    for (int kc = 0; kc < GK; kc += 32) {
        #pragma unroll
        for (int s = 0; s < 2; s++) {
            int f  = tid + s * 256;
            int r  = f >> 2;
            int sg = (f & 3) * 8;
            uint4 vh = Z, vl = Z;
            if (row0 + r < M) {
                vh = *(const uint4*)&Agh[(size_t)(row0 + r) * GK + kc + sg];
                vl = *(const uint4*)&Agl[(size_t)(row0 + r) * GK + kc + sg];
            }
            *(uint4*)&Ah[r][sg] = vh;
            *(uint4*)&Al[r][sg] = vl;
        }
        {
            int r  = tid >> 2;
            int sg = (tid & 3) * 8;
            uint4 vh = *(const uint4*)&Bgh[(size_t)(col0 + r) * GK + kc + sg];
            uint4 vl = *(const uint4*)&Bgl[(size_t)(col0 + r) * GK + kc + sg];
            *(uint4*)&Bh[r][sg] = vh;
            *(uint4*)&Bl[r][sg] = vl;
        }
        __syncthreads();

        #pragma unroll
        for (int ss = 0; ss < 2; ss++) {
            const int kb = ss * 16;
            uint32_t ah[2][4], al[2][4], bh[4][2], bl[4][2];
            #pragma unroll
            for (int t = 0; t < 2; t++) {
                int r1 = wm + t * 16 + gr;
                ah[t][0] = *(const uint32_t*)&Ah[r1    ][kb + tg * 2    ];
                ah[t][1] = *(const uint32_t*)&Ah[r1 + 8][kb + tg * 2    ];
                ah[t][2] = *(const uint32_t*)&Ah[r1    ][kb + tg * 2 + 8];
                ah[t][3] = *(const uint32_t*)&Ah[r1 + 8][kb + tg * 2 + 8];
                al[t][0] = *(const uint32_t*)&Al[r1    ][kb + tg * 2    ];
                al[t][1] = *(const uint32_t*)&Al[r1 + 8][kb + tg * 2    ];
                al[t][2] = *(const uint32_t*)&Al[r1    ][kb + tg * 2 + 8];
                al[t][3] = *(const uint32_t*)&Al[r1 + 8][kb + tg * 2 + 8];
            }
            #pragma unroll
            for (int u = 0; u < 4; u++) {
                int n1 = wn + u * 8 + gr;
                bh[u][0] = *(const uint32_t*)&Bh[n1][kb + tg * 2    ];
                bh[u][1] = *(const uint32_t*)&Bh[n1][kb + tg * 2 + 8];
                bl[u][0] = *(const uint32_t*)&Bl[n1][kb + tg * 2    ];
                bl[u][1] = *(const uint32_t*)&Bl[n1][kb + tg * 2 + 8];
            }
            #pragma unroll
            for (int t = 0; t < 2; t++)
                #pragma unroll
                for (int u = 0; u < 4; u++) {
                    mma_bf16(acc[t][u], ah[t], bh[u]);
                    mma_bf16(acc[t][u], ah[t], bl[u]);
                    mma_bf16(acc[t][u], al[t], bh[u]);
                }
        }
        __syncthreads();
    }

    #pragma unroll
    for (int t = 0; t < 2; t++) {
        #pragma unroll
        for (int u = 0; u < 4; u++) {
            int colg = col0 + wn + u * 8 + tg * 2;
            float b0 = bias[colg], b1 = bias[colg + 1];
            #pragma unroll
            for (int half = 0; half < 2; half++) {
                int rowg = row0 + wm + t * 16 + gr + half * 8;
                if (rowg >= M) continue;
                float x0 = acc[t][u][half * 2 + 0] + b0;
                float x1 = acc[t][u][half * 2 + 1] + b1;
                if (act) {
                    x0 = x0 / (1.0f + expf(-x0));
                    x1 = x1 / (1.0f + expf(-x1));
                    __nv_bfloat16 h0, l0, h1, l1;
                    split_bf(x0, h0, l0);
                    split_bf(x1, h1, l1);
                    *(__nv_bfloat162*)&Chh[(size_t)rowg * GK + colg] = __nv_bfloat162(h0, h1);
                    *(__nv_bfloat162*)&Chl[(size_t)rowg * GK + colg] = __nv_bfloat162(l0, l1);
                } else {
                    *(float2*)&Cf[(size_t)rowg * N + colg] = make_float2(x0, x1);
                }
            }
        }
    }
}

// ---------------------------------------------------------------------------
// Edge MMA kernel: CTA = 128 edges x 64 channels. grid = (ceil(E/128), 6).
// Phase A: sines per edge -> split bf16 smem A tile [128][KPAD] (k>=20 zero).
// MMA: validated fragment code, 1 K-block (2 substeps x 3 split terms).
// Epilogue: out[e,c] = (acc*k1_e + br[c]*k2_e) * inv[j_e, c]
// ---------------------------------------------------------------------------
#define EM 128

__global__ __launch_bounds__(256) void edge_mma_kernel(
    const float* __restrict__ dist,
    const int* __restrict__ nb,
    const __nv_bfloat16* __restrict__ Wrh, const __nv_bfloat16* __restrict__ Wrl,
    const float* __restrict__ br,
    const float* __restrict__ inv,
    float* __restrict__ out,
    int n_edges)
{
    __shared__ __nv_bfloat16 Ah[EM][40], Al[EM][40];
    __shared__ __nv_bfloat16 Bh[64][40], Bl[64][40];
    __shared__ __align__(16) float4 sm_meta[EM];     // (k1, k2, j_bits, -)

    const int tid  = threadIdx.x;
    const int warp = tid >> 5;
    const int l    = tid & 31;
    const int gr   = l >> 2;
    const int tg   = l & 3;
    const int wm   = (warp >> 1) * 32;
    const int wn   = (warp & 1) * 32;
    const int base = blockIdx.x * EM;
    const int col0 = blockIdx.y * 64;
    const int is64 = g_nbrs_is64;

    const int cnt = min(EM, n_edges - base);

    // ---- phase A: sines + meta (threads 0..127) ----
    if (tid < EM) {
        const int et = base + tid;
        const int e  = (et < n_edges) ? et : (n_edges - 1);
        const float d  = dist[e];
        const float th = d * 0.6283185307179586f;    // pi/5
        const float s1 = sinf(th);
        const float c1 = cosf(th);
        float env = (d < 5.0f) ? 0.5f * (c1 + 1.0f) : 0.0f;
        if (et >= n_edges) env = 0.0f;
        const int j = is64 ? nb[4 * (long long)e + 2] : nb[2 * (long long)e + 1];
        sm_meta[tid] = make_float4(env / d, env, __int_as_float(j), 0.0f);

        const float u = 2.0f * c1;
        float sp = 0.0f, sc = s1;
        #pragma unroll
        for (int n = 0; n < NRBF; n += 2) {
            __nv_bfloat16 h0, l0, h1, l1;
            split_bf(sc, h0, l0);
            float sn = fmaf(u, sc, -sp);
            sp = sc; sc = sn;
            split_bf(sc, h1, l1);
            sn = fmaf(u, sc, -sp);
            sp = sc; sc = sn;
            *(__nv_bfloat162*)&Ah[tid][n] = __nv_bfloat162(h0, h1);
            *(__nv_bfloat162*)&Al[tid][n] = __nv_bfloat162(l0, l1);
        }
        const __nv_bfloat162 z2 = __nv_bfloat162(__float2bfloat16(0.f), __float2bfloat16(0.f));
        #pragma unroll
        for (int n = NRBF; n < KPAD; n += 2) {
            *(__nv_bfloat162*)&Ah[tid][n] = z2;
            *(__nv_bfloat162*)&Al[tid][n] = z2;
        }
    }
    // ---- stage B (Wr^T tile 64xKPAD): 256 uint4 per buffer, 1 each ----
    {
        int r  = tid >> 2;
        int sg = (tid & 3) * 8;
        uint4 vh = *(const uint4*)&Wrh[(size_t)(col0 + r) * KPAD + sg];
        uint4 vl = *(const uint4*)&Wrl[(size_t)(col0 + r) * KPAD + sg];
        *(uint4*)&Bh[r][sg] = vh;
        *(uint4*)&Bl[r][sg] = vl;
    }
    __syncthreads();

    // ---- MMA: one K block of 32 (2 substeps), 3 split terms ----
    float acc[2][4][4];
    #pragma unroll
    for (int t = 0; t < 2; t++)
        #pragma unroll
        for (int u = 0; u < 4; u++)
            #pragma unroll
            for (int v = 0; v < 4; v++) acc[t][u][v] = 0.0f;

    #pragma unroll
    for (int ss = 0; ss < 2; ss++) {
        const int kb = ss * 16;
        uint32_t ah[2][4], al[2][4], bh[4][2], bl[4][2];
        #pragma unroll
        for (int t = 0; t < 2; t++) {
            int r1 = wm + t * 16 + gr;
            ah[t][0] = *(const uint32_t*)&Ah[r1    ][kb + tg * 2    ];
            ah[t][1] = *(const uint32_t*)&Ah[r1 + 8][kb + tg * 2    ];
            ah[t][2] = *(const uint32_t*)&Ah[r1    ][kb + tg * 2 + 8];
            ah[t][3] = *(const uint32_t*)&Ah[r1 + 8][kb + tg * 2 + 8];
            al[t][0] = *(const uint32_t*)&Al[r1    ][kb + tg * 2    ];
            al[t][1] = *(const uint32_t*)&Al[r1 + 8][kb + tg * 2    ];
            al[t][2] = *(const uint32_t*)&Al[r1    ][kb + tg * 2 + 8];
            al[t][3] = *(const uint32_t*)&Al[r1 + 8][kb + tg * 2 + 8];
        }
        #pragma unroll
        for (int u = 0; u < 4; u++) {
            int n1 = wn + u * 8 + gr;
            bh[u][0] = *(const uint32_t*)&Bh[n1][kb + tg * 2    ];
            bh[u][1] = *(const uint32_t*)&Bh[n1][kb + tg * 2 + 8];
            bl[u][0] = *(const uint32_t*)&Bl[n1][kb + tg * 2    ];
            bl[u][1] = *(const uint32_t*)&Bl[n1][kb + tg * 2 + 8];
        }
        #pragma unroll
        for (int t = 0; t < 2; t++)
            #pragma unroll
            for (int u = 0; u < 4; u++) {
                mma_bf16(acc[t][u], ah[t], bh[u]);
                mma_bf16(acc[t][u], ah[t], bl[u]);
                mma_bf16(acc[t][u], al[t], bh[u]);
            }
    }

    // ---- epilogue: gather + scale + store ----
    float2 brv[4];
    #pragma unroll
    for (int u = 0; u < 4; u++)
        brv[u] = *(const float2*)&br[col0 + wn + u * 8 + tg * 2];

    #pragma unroll
    for (int t = 0; t < 2; t++) {
        #pragma unroll
        for (int half = 0; half < 2; half++) {
            const int rt = wm + t * 16 + gr + half * 8;   // row in tile
            if (rt >= cnt) continue;
            const float4 meta = sm_meta[rt];
            const float k1 = meta.x, k2 = meta.y;
            const size_t jrow = (size_t)__float_as_int(meta.z) * FEAT3;
            const size_t orow = (size_t)(base + rt) * FEAT3;
            #pragma unroll
            for (int u = 0; u < 4; u++) {
                const int colg = col0 + wn + u * 8 + tg * 2;
                const float2 ph = *(const float2*)&inv[jrow + colg];
                const float x0 = acc[t][u][half * 2 + 0];
                const float x1 = acc[t][u][half * 2 + 1];
                float2 o;
                o.x = fmaf(x0, k1, brv[u].x * k2) * ph.x;
                o.y = fmaf(x1, k1, brv[u].y * k2) * ph.y;
                *(float2*)&out[orow + colg] = o;
            }
        }
    }
}

// ---------------------------------------------------------------------------
// kernel_launch
// ---------------------------------------------------------------------------
extern "C" void kernel_launch(void* const* d_in, const int* in_sizes, int n_in,
                              void* d_out, int out_size)
{
    const float* s_j  = (const float*)d_in[0];
    const float* dist = (const float*)d_in[1];
    const int*   nb   = (const int*)  d_in[2];
    const float* W1   = (const float*)d_in[3];
    const float* b1   = (const float*)d_in[4];
    const float* W2   = (const float*)d_in[5];
    const float* b2   = (const float*)d_in[6];
    const float* Wr   = (const float*)d_in[7];
    const float* br   = (const float*)d_in[8];
    float*       out  = (float*)d_out;

    const int n_nodes = in_sizes[0] / FEAT;
    const int n_edges = in_sizes[1];

    __nv_bfloat16 *sh, *sl, *hh, *hl, *w1h, *w1l, *w2h, *w2l, *wrh, *wrl;
    float* invbuf;
    cudaGetSymbolAddress((void**)&sh,  g_sh);
    cudaGetSymbolAddress((void**)&sl,  g_sl);
    cudaGetSymbolAddress((void**)&hh,  g_hh);
    cudaGetSymbolAddress((void**)&hl,  g_hl);
    cudaGetSymbolAddress((void**)&w1h, g_w1h);
    cudaGetSymbolAddress((void**)&w1l, g_w1l);
    cudaGetSymbolAddress((void**)&w2h, g_w2h);
    cudaGetSymbolAddress((void**)&w2l, g_w2l);
    cudaGetSymbolAddress((void**)&wrh, g_wrh);
    cudaGetSymbolAddress((void**)&wrl, g_wrl);
    cudaGetSymbolAddress((void**)&invbuf, g_inv);

    detect_nbrs_kernel<<<1, 32>>>((const unsigned int*)nb, in_sizes[2]);

    // pre-split inputs and weights (W1, W2, Wr)
    {
        int n4 = (n_nodes * FEAT) / 4;
        split_f32_kernel<<<(n4 + 255) / 256, 256>>>((const float4*)s_j, sh, sl, n4);
        int nw = FEAT * FEAT + FEAT3 * FEAT + FEAT3 * KPAD;
        split_w_kernel<<<(nw + 255) / 256, 256>>>(W1, W2, Wr);
    }
    // GEMM1: h = silu(s_j @ W1 + b1) -> split bf16 h
    {
        dim3 grid((n_nodes + 127) / 128, FEAT / 64);
        hgemm_kernel<<<grid, 256>>>(sh, sl, w1h, w1l, b1,
                                    nullptr, hh, hl, n_nodes, FEAT, /*act=*/1);
    }
    // GEMM2: inv = h @ W2 + b2 -> fp32
    {
        dim3 grid((n_nodes + 127) / 128, FEAT3 / 64);
        hgemm_kernel<<<grid, 256>>>(hh, hl, w2h, w2l, b2,
                                    invbuf, nullptr, nullptr, n_nodes, FEAT3, /*act=*/0);
    }
    // Edge MMA kernel
    {
        dim3 grid((n_edges + EM - 1) / EM, FEAT3 / 64);
        edge_mma_kernel<<<grid, 256>>>(dist, nb, wrh, wrl, br, invbuf, out, n_edges);
    }
}